// round 1
// baseline (speedup 1.0000x reference)
#include <cuda_runtime.h>
#include <cstdint>

#define DM   1024      // d_model
#define NH   16
#define DH   64
#define TSEQ 2048
#define BSZ  2
#define BT   (BSZ*TSEQ)   // 4096 rows

// Scratch (static device globals — no allocation)
__device__ float g_q[BSZ*NH*TSEQ*DH];   // [B,H,T,Dh]
__device__ float g_k[BSZ*NH*TSEQ*DH];
__device__ float g_v[BSZ*NH*TSEQ*DH];
__device__ float g_ao[BT*DM];           // attention out, [B,T,H*Dh]

// ---------------------------------------------------------------------------
// SGEMM body: C[128x128] tile, K-step 16, 256 threads, 8x8 micro-tile.
// A: [M,K] row-major, Bmat: [K,N] row-major.
// ---------------------------------------------------------------------------
#define GEMM_BODY(Aptr, Bptr, KDIM)                                            \
    __shared__ float As[16][132];                                              \
    __shared__ float Bs[16][128];                                              \
    const int tid = threadIdx.x;                                               \
    const int tr = tid >> 4, tc = tid & 15;                                    \
    const int m0 = blockIdx.y * 128;                                           \
    const int n0 = blockIdx.x * 128;                                           \
    float acc[8][8];                                                           \
    _Pragma("unroll") for (int i = 0; i < 8; i++)                              \
        _Pragma("unroll") for (int j = 0; j < 8; j++) acc[i][j] = 0.0f;        \
    for (int k0 = 0; k0 < (KDIM); k0 += 16) {                                  \
        _Pragma("unroll") for (int it = 0; it < 2; it++) {                     \
            int lin = tid + it * 256;                                          \
            int row = lin >> 2, c4 = (lin & 3) << 2;                           \
            float4 a4 = *(const float4*)&(Aptr)[(size_t)(m0+row)*(KDIM)+k0+c4];\
            As[c4+0][row] = a4.x; As[c4+1][row] = a4.y;                        \
            As[c4+2][row] = a4.z; As[c4+3][row] = a4.w;                        \
        }                                                                      \
        _Pragma("unroll") for (int it = 0; it < 2; it++) {                     \
            int lin = tid + it * 256;                                          \
            int row = lin >> 5, c4 = (lin & 31) << 2;                          \
            *(float4*)&Bs[row][c4] =                                           \
                *(const float4*)&(Bptr)[(size_t)(k0+row)*1024 + n0 + c4];      \
        }                                                                      \
        __syncthreads();                                                       \
        _Pragma("unroll") for (int kk = 0; kk < 16; kk++) {                    \
            float a[8], b[8];                                                  \
            *(float4*)&a[0] = *(const float4*)&As[kk][tr*8];                   \
            *(float4*)&a[4] = *(const float4*)&As[kk][tr*8+4];                 \
            *(float4*)&b[0] = *(const float4*)&Bs[kk][tc*8];                   \
            *(float4*)&b[4] = *(const float4*)&Bs[kk][tc*8+4];                 \
            _Pragma("unroll") for (int i = 0; i < 8; i++)                      \
                _Pragma("unroll") for (int j = 0; j < 8; j++)                  \
                    acc[i][j] = fmaf(a[i], b[j], acc[i][j]);                   \
        }                                                                      \
        __syncthreads();                                                       \
    }

// ---------------------------------------------------------------------------
// Kernel 1: fused QKV projection. z selects q/k/v; output scattered to
// [B,H,T,Dh] layout.
// ---------------------------------------------------------------------------
__global__ __launch_bounds__(256) void qkv_kernel(
    const float* __restrict__ x,
    const float* __restrict__ wq, const float* __restrict__ bq,
    const float* __restrict__ wk, const float* __restrict__ bk,
    const float* __restrict__ wv, const float* __restrict__ bv)
{
    const float* W; const float* bias; float* out;
    if (blockIdx.z == 0)      { W = wq; bias = bq; out = g_q; }
    else if (blockIdx.z == 1) { W = wk; bias = bk; out = g_k; }
    else                      { W = wv; bias = bv; out = g_v; }

    GEMM_BODY(x, W, DM)

    // epilogue: scatter to [B,H,T,Dh]
    const int nb = n0 + tc * 8;       // column base; 8-col group never crosses a head
    const int h  = nb >> 6;
    const int d  = nb & 63;
    float bb[8];
    #pragma unroll
    for (int j = 0; j < 8; j++) bb[j] = bias[nb + j];
    #pragma unroll
    for (int i = 0; i < 8; i++) {
        int m = m0 + tr * 8 + i;
        int b = m >> 11;              // / 2048
        int t = m & 2047;
        float* o = out + (((size_t)(b * NH + h) * TSEQ + t) << 6) + d;
        float4 v0 = make_float4(acc[i][0]+bb[0], acc[i][1]+bb[1],
                                acc[i][2]+bb[2], acc[i][3]+bb[3]);
        float4 v1 = make_float4(acc[i][4]+bb[4], acc[i][5]+bb[5],
                                acc[i][6]+bb[6], acc[i][7]+bb[7]);
        *(float4*)&o[0] = v0;
        *(float4*)&o[4] = v1;
    }
}

// ---------------------------------------------------------------------------
// Kernel 2: causal flash attention. One block per (q-tile 64, b*h).
// 256 threads, 4x4 micro-tiles over a 64x64 S tile. Online softmax.
// ---------------------------------------------------------------------------
__global__ __launch_bounds__(256) void attn_kernel()
{
    extern __shared__ float sm[];
    float* Qst = sm;                    // [64][64]  d-major (Q^T), pre-scaled
    float* Kst = Qst + 64 * 64;         // [64][68]  d-major (K^T)
    float* Vs  = Kst + 64 * 68;         // [64][64]  n-major (natural)
    float* Ps  = Vs  + 64 * 64;         // [64][68]  m-major (natural)

    const int tid = threadIdx.x;
    const int ty = tid >> 4, tx = tid & 15;
    const int qt = blockIdx.x;          // q tile 0..31
    const int bh = blockIdx.y;          // b*16+h

    const float* Q = g_q + (size_t)bh * TSEQ * DH + (size_t)qt * 64 * DH;
    const float* K = g_k + (size_t)bh * TSEQ * DH;
    const float* V = g_v + (size_t)bh * TSEQ * DH;

    const float scale = 0.125f;         // 1/sqrt(64)

    // load Q tile transposed, pre-scaled
    #pragma unroll
    for (int it = 0; it < 4; it++) {
        int lin = tid + it * 256;
        int r = lin >> 4;               // token row
        int c = (lin & 15) << 2;        // d
        float4 q4 = *(const float4*)&Q[r * DH + c];
        Qst[(c+0)*64 + r] = q4.x * scale;
        Qst[(c+1)*64 + r] = q4.y * scale;
        Qst[(c+2)*64 + r] = q4.z * scale;
        Qst[(c+3)*64 + r] = q4.w * scale;
    }

    float o[4][4];
    #pragma unroll
    for (int i = 0; i < 4; i++)
        #pragma unroll
        for (int j = 0; j < 4; j++) o[i][j] = 0.0f;
    float mrow[4] = {-1e30f, -1e30f, -1e30f, -1e30f};
    float lrow[4] = {0.f, 0.f, 0.f, 0.f};

    const int nkv = qt + 1;
    for (int kt = 0; kt < nkv; kt++) {
        __syncthreads();  // protect Kst/Vs from prior-iteration readers
        #pragma unroll
        for (int it = 0; it < 4; it++) {
            int lin = tid + it * 256;
            int r = lin >> 4;
            int c = (lin & 15) << 2;
            float4 k4 = *(const float4*)&K[(size_t)(kt*64 + r) * DH + c];
            Kst[(c+0)*68 + r] = k4.x;
            Kst[(c+1)*68 + r] = k4.y;
            Kst[(c+2)*68 + r] = k4.z;
            Kst[(c+3)*68 + r] = k4.w;
            float4 v4 = *(const float4*)&V[(size_t)(kt*64 + r) * DH + c];
            *(float4*)&Vs[r * 64 + c] = v4;
        }
        __syncthreads();

        // S = (Q*scale) @ K^T  -- 4x4 micro
        float s[4][4];
        #pragma unroll
        for (int i = 0; i < 4; i++)
            #pragma unroll
            for (int j = 0; j < 4; j++) s[i][j] = 0.0f;
        #pragma unroll 8
        for (int d = 0; d < 64; d++) {
            float a[4], b[4];
            *(float4*)a = *(const float4*)&Qst[d * 64 + ty * 4];
            *(float4*)b = *(const float4*)&Kst[d * 68 + tx * 4];
            #pragma unroll
            for (int i = 0; i < 4; i++)
                #pragma unroll
                for (int j = 0; j < 4; j++)
                    s[i][j] = fmaf(a[i], b[j], s[i][j]);
        }

        // causal mask on diagonal tile
        if (kt == qt) {
            #pragma unroll
            for (int i = 0; i < 4; i++)
                #pragma unroll
                for (int j = 0; j < 4; j++)
                    if (tx * 4 + j > ty * 4 + i) s[i][j] = -1e30f;
        }

        // online softmax per row (16 lanes per row -> width-16 shuffle reduce)
        #pragma unroll
        for (int i = 0; i < 4; i++) {
            float rm = fmaxf(fmaxf(s[i][0], s[i][1]), fmaxf(s[i][2], s[i][3]));
            #pragma unroll
            for (int off = 8; off > 0; off >>= 1)
                rm = fmaxf(rm, __shfl_xor_sync(0xffffffffu, rm, off, 16));
            float mnew = fmaxf(mrow[i], rm);
            float corr = __expf(mrow[i] - mnew);
            mrow[i] = mnew;
            float rs = 0.0f;
            #pragma unroll
            for (int j = 0; j < 4; j++) {
                s[i][j] = __expf(s[i][j] - mnew);
                rs += s[i][j];
            }
            #pragma unroll
            for (int off = 8; off > 0; off >>= 1)
                rs += __shfl_xor_sync(0xffffffffu, rs, off, 16);
            lrow[i] = lrow[i] * corr + rs;
            #pragma unroll
            for (int j = 0; j < 4; j++) o[i][j] *= corr;
        }

        // write P (natural layout) and sync before PV gemm
        #pragma unroll
        for (int i = 0; i < 4; i++)
            *(float4*)&Ps[(ty*4 + i) * 68 + tx*4] =
                make_float4(s[i][0], s[i][1], s[i][2], s[i][3]);
        __syncthreads();

        // O += P @ V
        #pragma unroll 8
        for (int n = 0; n < 64; n++) {
            float a[4], b[4];
            #pragma unroll
            for (int i = 0; i < 4; i++) a[i] = Ps[(ty*4 + i) * 68 + n];  // broadcast
            *(float4*)b = *(const float4*)&Vs[n * 64 + tx * 4];
            #pragma unroll
            for (int i = 0; i < 4; i++)
                #pragma unroll
                for (int j = 0; j < 4; j++)
                    o[i][j] = fmaf(a[i], b[j], o[i][j]);
        }
    }

    // normalize + write to [B,T,H*Dh]
    const int b = bh >> 4;
    const int h = bh & 15;
    #pragma unroll
    for (int i = 0; i < 4; i++) {
        int t = qt * 64 + ty * 4 + i;
        float inv = 1.0f / lrow[i];
        float4 r = make_float4(o[i][0]*inv, o[i][1]*inv, o[i][2]*inv, o[i][3]*inv);
        *(float4*)&g_ao[((size_t)(b * TSEQ + t)) * DM + h * DH + tx * 4] = r;
    }
}

// ---------------------------------------------------------------------------
// Kernel 3: output projection, row-major out + bias
// ---------------------------------------------------------------------------
__global__ __launch_bounds__(256) void oproj_kernel(
    const float* __restrict__ wo, const float* __restrict__ bo,
    float* __restrict__ out)
{
    GEMM_BODY(g_ao, wo, DM)

    const int nb = n0 + tc * 8;
    float bb[8];
    #pragma unroll
    for (int j = 0; j < 8; j++) bb[j] = bo[nb + j];
    #pragma unroll
    for (int i = 0; i < 8; i++) {
        size_t off = (size_t)(m0 + tr * 8 + i) * DM + nb;
        float4 v0 = make_float4(acc[i][0]+bb[0], acc[i][1]+bb[1],
                                acc[i][2]+bb[2], acc[i][3]+bb[3]);
        float4 v1 = make_float4(acc[i][4]+bb[4], acc[i][5]+bb[5],
                                acc[i][6]+bb[6], acc[i][7]+bb[7]);
        *(float4*)&out[off]     = v0;
        *(float4*)&out[off + 4] = v1;
    }
}

// ---------------------------------------------------------------------------
extern "C" void kernel_launch(void* const* d_in, const int* in_sizes, int n_in,
                              void* d_out, int out_size)
{
    const float* x  = (const float*)d_in[0];
    const float* wq = (const float*)d_in[1];
    const float* bq = (const float*)d_in[2];
    const float* wk = (const float*)d_in[3];
    const float* bk = (const float*)d_in[4];
    const float* wv = (const float*)d_in[5];
    const float* bv = (const float*)d_in[6];
    const float* wo = (const float*)d_in[7];
    const float* bo = (const float*)d_in[8];
    float* out = (float*)d_out;

    static const int ATTN_SMEM = (64*64 + 64*68 + 64*64 + 64*68) * 4;  // 67584
    cudaFuncSetAttribute(attn_kernel,
                         cudaFuncAttributeMaxDynamicSharedMemorySize, ATTN_SMEM);

    dim3 gQKV(DM / 128, BT / 128, 3);        // (8, 32, 3)
    qkv_kernel<<<gQKV, 256>>>(x, wq, bq, wk, bk, wv, bv);

    dim3 gA(TSEQ / 64, BSZ * NH);            // (32, 32)
    attn_kernel<<<gA, 256, ATTN_SMEM>>>();

    dim3 gO(DM / 128, BT / 128);             // (8, 32)
    oproj_kernel<<<gO, 256>>>(wo, bo, out);
}

// round 4
// speedup vs baseline: 2.2933x; 2.2933x over previous
#include <cuda_runtime.h>
#include <cuda_bf16.h>
#include <cstdint>

#define DM   1024
#define NH   16
#define DH   64
#define TSEQ 2048
#define BSZ  2
#define BT   (BSZ*TSEQ)

// ---------------------------------------------------------------------------
// Scratch (static device globals — no allocation). hi/lo bf16 stored as words.
// ---------------------------------------------------------------------------
__device__ __align__(16) uint32_t g_x_hi[BT*DM/2],  g_x_lo[BT*DM/2];
__device__ __align__(16) uint32_t g_w_hi[4*DM*DM/2], g_w_lo[4*DM*DM/2]; // [z][N][K]
__device__ __align__(16) uint32_t g_q_hi[BSZ*NH*TSEQ*DH/2], g_q_lo[BSZ*NH*TSEQ*DH/2];
__device__ __align__(16) uint32_t g_k_hi[BSZ*NH*TSEQ*DH/2], g_k_lo[BSZ*NH*TSEQ*DH/2];
__device__ __align__(16) float    g_v[BSZ*NH*TSEQ*DH];
__device__ __align__(16) uint32_t g_ao_hi[BT*DM/2], g_ao_lo[BT*DM/2];

// ---------------------------------------------------------------------------
// helpers
// ---------------------------------------------------------------------------
__device__ __forceinline__ uint32_t smem_u32(const void* p) {
    uint32_t a;
    asm("{ .reg .u64 t; cvta.to.shared.u64 t, %1; cvt.u32.u64 %0, t; }"
        : "=r"(a) : "l"(p));
    return a;
}

// pack two floats into bf16x2: lower half = e0, upper half = e1
__device__ __forceinline__ uint32_t pack2(float e0, float e1) {
    uint32_t r;
    asm("cvt.rn.bf16x2.f32 %0, %1, %2;" : "=r"(r) : "f"(e1), "f"(e0));
    return r;
}

// split pair (x0,x1) into hi bf16x2 + lo (residual) bf16x2
__device__ __forceinline__ void split2(float x0, float x1, uint32_t& hi, uint32_t& lo) {
    hi = pack2(x0, x1);
    float h0 = __uint_as_float(hi << 16);
    float h1 = __uint_as_float(hi & 0xffff0000u);
    lo = pack2(x0 - h0, x1 - h1);
}

// D(16x8) += A(16x16) * B(16x8), bf16 in, fp32 acc. A row-major, B col-major.
__device__ __forceinline__ void mma16(float* d, const uint32_t* a, const uint32_t* b) {
    asm volatile(
        "mma.sync.aligned.m16n8k16.row.col.f32.bf16.bf16.f32 "
        "{%0,%1,%2,%3}, {%4,%5,%6,%7}, {%8,%9}, {%0,%1,%2,%3};"
        : "+f"(d[0]), "+f"(d[1]), "+f"(d[2]), "+f"(d[3])
        : "r"(a[0]), "r"(a[1]), "r"(a[2]), "r"(a[3]), "r"(b[0]), "r"(b[1]));
}

__device__ __forceinline__ void cp16(uint32_t saddr, const void* g) {
    asm volatile("cp.async.cg.shared.global [%0], [%1], 16;"
                 :: "r"(saddr), "l"(g) : "memory");
}
#define CP_COMMIT() asm volatile("cp.async.commit_group;" ::: "memory")

// ---------------------------------------------------------------------------
// GEMM: C[128x128] = A[128,1024] @ B[128,1024]^T, both K-major bf16 hi/lo.
// K-chunk 32 elems. SMEM row: 16 words hi | 16 words lo | 4 pad (stride 36).
// 8 warps: 2(M)x4(N), warp tile 64x32. 3-term bf16 MMA.
// ---------------------------------------------------------------------------
__device__ __forceinline__ void gemm_stage(uint32_t sbase, int buf,
                                           const uint32_t* Ahi, const uint32_t* Alo,
                                           const uint32_t* Bhi, const uint32_t* Blo,
                                           int k0) {
    const int tid = threadIdx.x;
    const uint32_t s = sbase + (uint32_t)buf * 36864u;
    // 2048 cp16 per stage: A(1024) + B(1024); 8 per thread
    #pragma unroll
    for (int it = 0; it < 8; it++) {
        int lin = it * 256 + tid;
        int isB = lin >> 10;
        int r   = (lin >> 3) & 127;
        int c   = lin & 7;
        int ishi = (c < 4);
        int cc  = c & 3;
        const uint32_t* src = isB ? (ishi ? Bhi : Blo) : (ishi ? Ahi : Alo);
        // word offsets: gmem row r has DM/2=512 words; chunk cc covers words cc*4..+3
        const uint32_t* g = src + (size_t)r * 512 + (k0 >> 1) + cc * 4;
        uint32_t dstw = (uint32_t)(isB * 4608 + r * 36 + (ishi ? 0 : 16) + cc * 4);
        cp16(s + dstw * 4u, g);
    }
    CP_COMMIT();
}

__device__ __forceinline__ void gemm_compute(const uint32_t* __restrict__ As,
                                             const uint32_t* __restrict__ Bs,
                                             int wm, int wn, int gid, int tig,
                                             float acc[4][4][4]) {
    #pragma unroll
    for (int kk = 0; kk < 2; kk++) {
        const int w = kk * 8 + tig;
        uint32_t bh[4][2], bl[4][2];
        #pragma unroll
        for (int nt = 0; nt < 4; nt++) {
            const uint32_t* br = Bs + (wn * 32 + nt * 8 + gid) * 36;
            bh[nt][0] = br[w];      bh[nt][1] = br[w + 4];
            bl[nt][0] = br[16 + w]; bl[nt][1] = br[16 + w + 4];
        }
        #pragma unroll
        for (int mt = 0; mt < 4; mt++) {
            const int r = wm * 64 + mt * 16 + gid;
            uint32_t ah[4], al[4];
            ah[0] = As[r * 36 + w];            ah[1] = As[(r + 8) * 36 + w];
            ah[2] = As[r * 36 + w + 4];        ah[3] = As[(r + 8) * 36 + w + 4];
            al[0] = As[r * 36 + 16 + w];       al[1] = As[(r + 8) * 36 + 16 + w];
            al[2] = As[r * 36 + 16 + w + 4];   al[3] = As[(r + 8) * 36 + 16 + w + 4];
            #pragma unroll
            for (int nt = 0; nt < 4; nt++) {
                mma16(acc[mt][nt], ah, bh[nt]);
                mma16(acc[mt][nt], ah, bl[nt]);
                mma16(acc[mt][nt], al, bh[nt]);
            }
        }
    }
}

__device__ __forceinline__ void gemm_main(const uint32_t* Ahi, const uint32_t* Alo,
                                          const uint32_t* Bhi, const uint32_t* Blo,
                                          float acc[4][4][4]) {
    extern __shared__ uint32_t dsm[];
    const uint32_t sbase = smem_u32(dsm);

    gemm_stage(sbase, 0, Ahi, Alo, Bhi, Blo, 0);
    gemm_stage(sbase, 1, Ahi, Alo, Bhi, Blo, 32);

    const int tid = threadIdx.x;
    const int wid = tid >> 5, lane = tid & 31;
    const int gid = lane >> 2, tig = lane & 3;
    const int wm = wid & 1, wn = wid >> 1;

    #pragma unroll 1
    for (int kt = 0; kt < 32; kt++) {
        if (kt < 30) asm volatile("cp.async.wait_group 1;" ::: "memory");
        else         asm volatile("cp.async.wait_group 0;" ::: "memory");
        __syncthreads();
        const uint32_t* As = dsm + (kt & 1) * 9216;
        const uint32_t* Bs = As + 4608;
        gemm_compute(As, Bs, wm, wn, gid, tig, acc);
        __syncthreads();
        if (kt + 2 < 32)
            gemm_stage(sbase, kt & 1, Ahi, Alo, Bhi, Blo, (kt + 2) * 32);
    }
}

// ---------------------------------------------------------------------------
// Kernel 0a: split x -> x_hi, x_lo
// ---------------------------------------------------------------------------
__global__ __launch_bounds__(256) void split_x_kernel(const float* __restrict__ x) {
    int i = (blockIdx.x * 256 + threadIdx.x) * 4;
    float4 v = *(const float4*)&x[i];
    uint32_t h0, l0, h1, l1;
    split2(v.x, v.y, h0, l0);
    split2(v.z, v.w, h1, l1);
    *(uint2*)&g_x_hi[i >> 1] = make_uint2(h0, h1);
    *(uint2*)&g_x_lo[i >> 1] = make_uint2(l0, l1);
}

// ---------------------------------------------------------------------------
// Kernel 0b: transpose+split weights  W[k][n] -> w_hi/lo[z][n][k]
// ---------------------------------------------------------------------------
__global__ __launch_bounds__(256) void transpose_split_kernel(
    const float* __restrict__ wq, const float* __restrict__ wk,
    const float* __restrict__ wv, const float* __restrict__ wo)
{
    __shared__ float tile[32][33];
    const float* src = (blockIdx.z == 0) ? wq : (blockIdx.z == 1) ? wk
                       : (blockIdx.z == 2) ? wv : wo;
    __nv_bfloat16* dh = (__nv_bfloat16*)(g_w_hi + (size_t)blockIdx.z * DM * DM / 2);
    __nv_bfloat16* dl = (__nv_bfloat16*)(g_w_lo + (size_t)blockIdx.z * DM * DM / 2);
    int x = blockIdx.x * 32 + threadIdx.x;
    int y0 = blockIdx.y * 32;
    #pragma unroll
    for (int i = threadIdx.y; i < 32; i += 8)
        tile[i][threadIdx.x] = src[(size_t)(y0 + i) * DM + x];
    __syncthreads();
    int xo = blockIdx.y * 32 + threadIdx.x;
    int yo0 = blockIdx.x * 32;
    #pragma unroll
    for (int i = threadIdx.y; i < 32; i += 8) {
        float v = tile[threadIdx.x][i];
        __nv_bfloat16 h = __float2bfloat16(v);
        dh[(size_t)(yo0 + i) * DM + xo] = h;
        dl[(size_t)(yo0 + i) * DM + xo] = __float2bfloat16(v - __bfloat162float(h));
    }
}

// ---------------------------------------------------------------------------
// Kernel 1: QKV projection. grid (8, 32, 3).
// q (z=0): pre-scaled by 0.125, split -> g_q_hi/lo  [B,H,T,Dh]
// k (z=1): split -> g_k_hi/lo; v (z=2): fp32 -> g_v
// ---------------------------------------------------------------------------
__global__ __launch_bounds__(256) void qkv_mma_kernel(
    const float* __restrict__ bq, const float* __restrict__ bk,
    const float* __restrict__ bv)
{
    const int z = blockIdx.z;
    const float* bias = (z == 0) ? bq : (z == 1) ? bk : bv;
    const int m0 = blockIdx.y * 128, n0 = blockIdx.x * 128;

    float acc[4][4][4];
    #pragma unroll
    for (int mt = 0; mt < 4; mt++)
        #pragma unroll
        for (int nt = 0; nt < 4; nt++)
            #pragma unroll
            for (int i = 0; i < 4; i++) acc[mt][nt][i] = 0.0f;

    gemm_main(g_x_hi + (size_t)m0 * 512, g_x_lo + (size_t)m0 * 512,
              g_w_hi + (size_t)z * DM * DM / 2 + (size_t)n0 * 512,
              g_w_lo + (size_t)z * DM * DM / 2 + (size_t)n0 * 512, acc);

    const int tid = threadIdx.x;
    const int wid = tid >> 5, lane = tid & 31;
    const int gid = lane >> 2, tig = lane & 3;
    const int wm = wid & 1, wn = wid >> 1;

    #pragma unroll
    for (int nt = 0; nt < 4; nt++) {
        int col = n0 + wn * 32 + nt * 8 + 2 * tig;
        int h = col >> 6, d = col & 63;
        float b0 = bias[col], b1 = bias[col + 1];
        #pragma unroll
        for (int mt = 0; mt < 4; mt++) {
            int row = m0 + wm * 64 + mt * 16 + gid;
            int b = row >> 11, t = row & 2047;
            size_t base = ((size_t)(b * NH + h) * TSEQ + t) << 6;  // element idx
            if (z == 2) {
                *(float2*)&g_v[base + d] =
                    make_float2(acc[mt][nt][0] + b0, acc[mt][nt][1] + b1);
                *(float2*)&g_v[base + (8 << 6) + d] =
                    make_float2(acc[mt][nt][2] + b0, acc[mt][nt][3] + b1);
            } else {
                float sc = (z == 0) ? 0.125f : 1.0f;
                uint32_t *ph = (z == 0) ? g_q_hi : g_k_hi;
                uint32_t *pl = (z == 0) ? g_q_lo : g_k_lo;
                uint32_t hi, lo;
                size_t w0 = (base + d) >> 1;
                split2((acc[mt][nt][0] + b0) * sc, (acc[mt][nt][1] + b1) * sc, hi, lo);
                ph[w0] = hi; pl[w0] = lo;
                size_t w1 = (base + (8 << 6) + d) >> 1;
                split2((acc[mt][nt][2] + b0) * sc, (acc[mt][nt][3] + b1) * sc, hi, lo);
                ph[w1] = hi; pl[w1] = lo;
            }
        }
    }
}

// ---------------------------------------------------------------------------
// Kernel 3: O projection. grid (8, 32). A = g_ao_hi/lo, out fp32 + bias.
// ---------------------------------------------------------------------------
__global__ __launch_bounds__(256) void oproj_mma_kernel(
    const float* __restrict__ bo, float* __restrict__ out)
{
    const int m0 = blockIdx.y * 128, n0 = blockIdx.x * 128;

    float acc[4][4][4];
    #pragma unroll
    for (int mt = 0; mt < 4; mt++)
        #pragma unroll
        for (int nt = 0; nt < 4; nt++)
            #pragma unroll
            for (int i = 0; i < 4; i++) acc[mt][nt][i] = 0.0f;

    gemm_main(g_ao_hi + (size_t)m0 * 512, g_ao_lo + (size_t)m0 * 512,
              g_w_hi + (size_t)3 * DM * DM / 2 + (size_t)n0 * 512,
              g_w_lo + (size_t)3 * DM * DM / 2 + (size_t)n0 * 512, acc);

    const int tid = threadIdx.x;
    const int wid = tid >> 5, lane = tid & 31;
    const int gid = lane >> 2, tig = lane & 3;
    const int wm = wid & 1, wn = wid >> 1;

    #pragma unroll
    for (int nt = 0; nt < 4; nt++) {
        int col = n0 + wn * 32 + nt * 8 + 2 * tig;
        float b0 = bo[col], b1 = bo[col + 1];
        #pragma unroll
        for (int mt = 0; mt < 4; mt++) {
            int row = m0 + wm * 64 + mt * 16 + gid;
            *(float2*)&out[(size_t)row * DM + col] =
                make_float2(acc[mt][nt][0] + b0, acc[mt][nt][1] + b1);
            *(float2*)&out[(size_t)(row + 8) * DM + col] =
                make_float2(acc[mt][nt][2] + b0, acc[mt][nt][3] + b1);
        }
    }
}

// ---------------------------------------------------------------------------
// Kernel 2: causal flash attention, bf16 3-term MMA, register-resident P.
// BLOCK_M=128 (8 warps x 16 rows), KV tile 64, double-buffered.
// SMEM per buf: Ks[64 tok][68w: 32 hi d-pairs | 32 lo | 4 pad]
//               Vt[64 d  ][68w: 32 hi t-pairs | 32 lo | 4 pad]
// ---------------------------------------------------------------------------
__global__ __launch_bounds__(256) void attn_mma_kernel()
{
    extern __shared__ uint32_t dsm[];
    const uint32_t sbase = smem_u32(dsm);

    const int tid = threadIdx.x;
    const int wid = tid >> 5, lane = tid & 31;
    const int gid = lane >> 2, tig = lane & 3;
    const int qt = 15 - (int)blockIdx.x;     // heavy tiles first
    const int bh = blockIdx.y;

    const uint32_t* qh = g_q_hi + (size_t)bh * TSEQ * 32 + (size_t)qt * 128 * 32;
    const uint32_t* ql = g_q_lo + (size_t)bh * TSEQ * 32 + (size_t)qt * 128 * 32;
    const uint32_t* kh = g_k_hi + (size_t)bh * TSEQ * 32;
    const uint32_t* kl = g_k_lo + (size_t)bh * TSEQ * 32;
    const float*    V  = g_v    + (size_t)bh * TSEQ * DH;

    const int r0l = wid * 16 + gid;          // local q row

    // Q fragments (pre-scaled in QKV): qfh/qfl[ks][0..3]
    uint32_t qfh[4][4], qfl[4][4];
    #pragma unroll
    for (int ks = 0; ks < 4; ks++) {
        int w = ks * 8 + tig;
        qfh[ks][0] = qh[r0l * 32 + w];        qfl[ks][0] = ql[r0l * 32 + w];
        qfh[ks][1] = qh[(r0l + 8) * 32 + w];  qfl[ks][1] = ql[(r0l + 8) * 32 + w];
        qfh[ks][2] = qh[r0l * 32 + w + 4];    qfl[ks][2] = ql[r0l * 32 + w + 4];
        qfh[ks][3] = qh[(r0l + 8) * 32 + w + 4]; qfl[ks][3] = ql[(r0l + 8) * 32 + w + 4];
    }

    float o[8][4];
    #pragma unroll
    for (int nt = 0; nt < 8; nt++)
        #pragma unroll
        for (int i = 0; i < 4; i++) o[nt][i] = 0.0f;
    float m0 = -1e30f, m1 = -1e30f, l0 = 0.0f, l1 = 0.0f;

    const int nkv = 2 * qt + 2;

    // staging: buf b at dsm + b*8704 words; Ks first 4352 words, Vt next 4352
    auto stage = [&](int kt, int buf) {
        uint32_t s = sbase + (uint32_t)buf * 34816u;           // bytes
        // K: 1024 cp16 (64 rows x 8 hi + 8 lo chunks)
        #pragma unroll
        for (int it = 0; it < 4; it++) {
            int lin = it * 256 + tid;
            int r = lin >> 4, c = lin & 15;
            int ishi = (c < 8);
            int cc = c & 7;
            const uint32_t* src = (ishi ? kh : kl) + (size_t)(kt * 64 + r) * 32 + cc * 4;
            uint32_t dstw = (uint32_t)(r * 68 + (ishi ? 0 : 32) + cc * 4);
            cp16(s + dstw * 4u, src);
        }
        CP_COMMIT();
        // V: transpose + split, STS (visible after next __syncthreads)
        uint32_t vbase = s + 4352u * 4u;
        #pragma unroll
        for (int it = 0; it < 8; it++) {
            int lin = it * 256 + tid;
            int d = lin & 63, tp = lin >> 6;
            float f0 = V[(size_t)(kt * 64 + 2 * tp) * DH + d];
            float f1 = V[(size_t)(kt * 64 + 2 * tp + 1) * DH + d];
            uint32_t hi, lo;
            split2(f0, f1, hi, lo);
            *(uint32_t*)((char*)0 + 0); // placeholder removed below
            // direct smem stores:
            asm volatile("st.shared.b32 [%0], %1;" :: "r"(vbase + (uint32_t)(d * 68 + tp) * 4u), "r"(hi) : "memory");
            asm volatile("st.shared.b32 [%0], %1;" :: "r"(vbase + (uint32_t)(d * 68 + 32 + tp) * 4u), "r"(lo) : "memory");
        }
    };
    // remove placeholder: (kept structure minimal below)

    stage(0, 0);
    stage(1, 1);

    #pragma unroll 1
    for (int kt = 0; kt < nkv; kt++) {
        if (kt + 1 < nkv) asm volatile("cp.async.wait_group 1;" ::: "memory");
        else              asm volatile("cp.async.wait_group 0;" ::: "memory");
        __syncthreads();

        const uint32_t* Ks = dsm + (kt & 1) * 8704;
        const uint32_t* Vt = Ks + 4352;

        // ---- S = Q @ K^T (3-term bf16) ----
        float s[8][4];
        #pragma unroll
        for (int nt = 0; nt < 8; nt++)
            #pragma unroll
            for (int i = 0; i < 4; i++) s[nt][i] = 0.0f;
        #pragma unroll
        for (int ks = 0; ks < 4; ks++) {
            int w = ks * 8 + tig;
            #pragma unroll
            for (int nt = 0; nt < 8; nt++) {
                const uint32_t* kr = Ks + (nt * 8 + gid) * 68;
                uint32_t bh2[2] = { kr[w], kr[w + 4] };
                uint32_t bl2[2] = { kr[32 + w], kr[32 + w + 4] };
                mma16(s[nt], qfh[ks], bh2);
                mma16(s[nt], qfh[ks], bl2);
                mma16(s[nt], qfl[ks], bh2);
            }
        }

        // ---- causal mask (near-diagonal tiles only) ----
        if (kt >= 2 * qt) {
            int row0 = qt * 128 + r0l;
            #pragma unroll
            for (int nt = 0; nt < 8; nt++) {
                int c0 = kt * 64 + nt * 8 + 2 * tig;
                if (c0 > row0)         s[nt][0] = -1e30f;
                if (c0 + 1 > row0)     s[nt][1] = -1e30f;
                if (c0 > row0 + 8)     s[nt][2] = -1e30f;
                if (c0 + 1 > row0 + 8) s[nt][3] = -1e30f;
            }
        }

        // ---- online softmax (rows r0l, r0l+8; 4 lanes/row) ----
        {
            float rm0 = -1e30f, rm1 = -1e30f;
            #pragma unroll
            for (int nt = 0; nt < 8; nt++) {
                rm0 = fmaxf(rm0, fmaxf(s[nt][0], s[nt][1]));
                rm1 = fmaxf(rm1, fmaxf(s[nt][2], s[nt][3]));
            }
            #pragma unroll
            for (int off = 1; off <= 2; off <<= 1) {
                rm0 = fmaxf(rm0, __shfl_xor_sync(0xffffffffu, rm0, off, 4));
                rm1 = fmaxf(rm1, __shfl_xor_sync(0xffffffffu, rm1, off, 4));
            }
            float mn0 = fmaxf(m0, rm0), mn1 = fmaxf(m1, rm1);
            float cr0 = __expf(m0 - mn0), cr1 = __expf(m1 - mn1);
            m0 = mn0; m1 = mn1;
            float rs0 = 0.0f, rs1 = 0.0f;
            #pragma unroll
            for (int nt = 0; nt < 8; nt++) {
                s[nt][0] = __expf(s[nt][0] - mn0);
                s[nt][1] = __expf(s[nt][1] - mn0);
                s[nt][2] = __expf(s[nt][2] - mn1);
                s[nt][3] = __expf(s[nt][3] - mn1);
                rs0 += s[nt][0] + s[nt][1];
                rs1 += s[nt][2] + s[nt][3];
            }
            #pragma unroll
            for (int off = 1; off <= 2; off <<= 1) {
                rs0 += __shfl_xor_sync(0xffffffffu, rs0, off, 4);
                rs1 += __shfl_xor_sync(0xffffffffu, rs1, off, 4);
            }
            l0 = l0 * cr0 + rs0;
            l1 = l1 * cr1 + rs1;
            #pragma unroll
            for (int nt = 0; nt < 8; nt++) {
                o[nt][0] *= cr0; o[nt][1] *= cr0;
                o[nt][2] *= cr1; o[nt][3] *= cr1;
            }
        }

        // ---- O += P @ V : P stays in registers (C-frag == A-frag layout) ----
        #pragma unroll
        for (int ks = 0; ks < 4; ks++) {
            uint32_t ph[4], pl[4];
            split2(s[2*ks][0],   s[2*ks][1],   ph[0], pl[0]);
            split2(s[2*ks][2],   s[2*ks][3],   ph[1], pl[1]);
            split2(s[2*ks+1][0], s[2*ks+1][1], ph[2], pl[2]);
            split2(s[2*ks+1][2], s[2*ks+1][3], ph[3], pl[3]);
            int w = ks * 8 + tig;
            #pragma unroll
            for (int nt = 0; nt < 8; nt++) {
                const uint32_t* vr = Vt + (nt * 8 + gid) * 68;
                uint32_t bh2[2] = { vr[w], vr[w + 4] };
                uint32_t bl2[2] = { vr[32 + w], vr[32 + w + 4] };
                mma16(o[nt], ph, bh2);
                mma16(o[nt], ph, bl2);
                mma16(o[nt], pl, bh2);
            }
        }

        __syncthreads();
        if (kt + 2 < nkv) stage(kt + 2, kt & 1);
    }

    // ---- epilogue: normalize, split, write g_ao_hi/lo [B,T,H*Dh] ----
    const int b = bh >> 4, h = bh & 15;
    const float inv0 = 1.0f / l0, inv1 = 1.0f / l1;
    size_t row0 = (size_t)(b * TSEQ + qt * 128 + r0l);
    #pragma unroll
    for (int nt = 0; nt < 8; nt++) {
        int c = nt * 8 + 2 * tig;                 // d within head
        uint32_t hi, lo;
        size_t w0 = (row0 * DM + h * 64 + c) >> 1;
        split2(o[nt][0] * inv0, o[nt][1] * inv0, hi, lo);
        g_ao_hi[w0] = hi; g_ao_lo[w0] = lo;
        size_t w1 = ((row0 + 8) * DM + h * 64 + c) >> 1;
        split2(o[nt][2] * inv1, o[nt][3] * inv1, hi, lo);
        g_ao_hi[w1] = hi; g_ao_lo[w1] = lo;
    }
}

// ---------------------------------------------------------------------------
extern "C" void kernel_launch(void* const* d_in, const int* in_sizes, int n_in,
                              void* d_out, int out_size)
{
    const float* x  = (const float*)d_in[0];
    const float* wq = (const float*)d_in[1];
    const float* bq = (const float*)d_in[2];
    const float* wk = (const float*)d_in[3];
    const float* bk = (const float*)d_in[4];
    const float* wv = (const float*)d_in[5];
    const float* bv = (const float*)d_in[6];
    const float* wo = (const float*)d_in[7];
    const float* bo = (const float*)d_in[8];
    float* out = (float*)d_out;

    static const int GEMM_SMEM = 73728;   // 2 stages x (A 18432 + B 18432)
    static const int ATTN_SMEM = 69632;   // 2 bufs x (Ks 17408 + Vt 17408)

    cudaFuncSetAttribute(qkv_mma_kernel,
                         cudaFuncAttributeMaxDynamicSharedMemorySize, GEMM_SMEM);
    cudaFuncSetAttribute(oproj_mma_kernel,
                         cudaFuncAttributeMaxDynamicSharedMemorySize, GEMM_SMEM);
    cudaFuncSetAttribute(attn_mma_kernel,
                         cudaFuncAttributeMaxDynamicSharedMemorySize, ATTN_SMEM);

    split_x_kernel<<<BT * DM / 1024, 256>>>(x);
    transpose_split_kernel<<<dim3(32, 32, 4), dim3(32, 8)>>>(wq, wk, wv, wo);

    qkv_mma_kernel<<<dim3(8, 32, 3), 256, GEMM_SMEM>>>(bq, bk, bv);

    attn_mma_kernel<<<dim3(16, 32), 256, ATTN_SMEM>>>();

    oproj_mma_kernel<<<dim3(8, 32), 256, GEMM_SMEM>>>(bo, out);
}

// round 5
// speedup vs baseline: 2.6504x; 1.1557x over previous
#include <cuda_runtime.h>
#include <cuda_bf16.h>
#include <cstdint>

#define DM   1024
#define NH   16
#define DH   64
#define TSEQ 2048
#define BSZ  2
#define BT   (BSZ*TSEQ)

// ---------------------------------------------------------------------------
// Scratch (static device globals — no allocation). hi/lo bf16 stored as words.
// ---------------------------------------------------------------------------
__device__ __align__(16) uint32_t g_x_hi[BT*DM/2],  g_x_lo[BT*DM/2];
__device__ __align__(16) uint32_t g_w_hi[4*DM*DM/2], g_w_lo[4*DM*DM/2]; // [z][N][K]
__device__ __align__(16) uint32_t g_q_hi[BSZ*NH*TSEQ*DH/2], g_q_lo[BSZ*NH*TSEQ*DH/2];
__device__ __align__(16) uint32_t g_k_hi[BSZ*NH*TSEQ*DH/2], g_k_lo[BSZ*NH*TSEQ*DH/2];
__device__ __align__(16) float    g_v[BSZ*NH*TSEQ*DH];
__device__ __align__(16) uint32_t g_vt_hi[BSZ*NH*DH*(TSEQ/2)], g_vt_lo[BSZ*NH*DH*(TSEQ/2)];
__device__ __align__(16) uint32_t g_ao_hi[BT*DM/2], g_ao_lo[BT*DM/2];

// ---------------------------------------------------------------------------
// helpers
// ---------------------------------------------------------------------------
__device__ __forceinline__ uint32_t smem_u32(const void* p) {
    uint32_t a;
    asm("{ .reg .u64 t; cvta.to.shared.u64 t, %1; cvt.u32.u64 %0, t; }"
        : "=r"(a) : "l"(p));
    return a;
}

__device__ __forceinline__ uint32_t pack2(float e0, float e1) {
    uint32_t r;
    asm("cvt.rn.bf16x2.f32 %0, %1, %2;" : "=r"(r) : "f"(e1), "f"(e0));
    return r;
}

__device__ __forceinline__ void split2(float x0, float x1, uint32_t& hi, uint32_t& lo) {
    hi = pack2(x0, x1);
    float h0 = __uint_as_float(hi << 16);
    float h1 = __uint_as_float(hi & 0xffff0000u);
    lo = pack2(x0 - h0, x1 - h1);
}

__device__ __forceinline__ void mma16(float* d, const uint32_t* a, const uint32_t* b) {
    asm volatile(
        "mma.sync.aligned.m16n8k16.row.col.f32.bf16.bf16.f32 "
        "{%0,%1,%2,%3}, {%4,%5,%6,%7}, {%8,%9}, {%0,%1,%2,%3};"
        : "+f"(d[0]), "+f"(d[1]), "+f"(d[2]), "+f"(d[3])
        : "r"(a[0]), "r"(a[1]), "r"(a[2]), "r"(a[3]), "r"(b[0]), "r"(b[1]));
}

__device__ __forceinline__ void cp16(uint32_t saddr, const void* g) {
    asm volatile("cp.async.cg.shared.global [%0], [%1], 16;"
                 :: "r"(saddr), "l"(g) : "memory");
}
#define CP_COMMIT() asm volatile("cp.async.commit_group;" ::: "memory")

// ---------------------------------------------------------------------------
// GEMM: C[128x128] = A[128,1024] @ B[128,1024]^T, both K-major bf16 hi/lo.
// ---------------------------------------------------------------------------
__device__ __forceinline__ void gemm_stage(uint32_t sbase, int buf,
                                           const uint32_t* Ahi, const uint32_t* Alo,
                                           const uint32_t* Bhi, const uint32_t* Blo,
                                           int k0) {
    const int tid = threadIdx.x;
    const uint32_t s = sbase + (uint32_t)buf * 36864u;
    #pragma unroll
    for (int it = 0; it < 8; it++) {
        int lin = it * 256 + tid;
        int isB = lin >> 10;
        int r   = (lin >> 3) & 127;
        int c   = lin & 7;
        int ishi = (c < 4);
        int cc  = c & 3;
        const uint32_t* src = isB ? (ishi ? Bhi : Blo) : (ishi ? Ahi : Alo);
        const uint32_t* g = src + (size_t)r * 512 + (k0 >> 1) + cc * 4;
        uint32_t dstw = (uint32_t)(isB * 4608 + r * 36 + (ishi ? 0 : 16) + cc * 4);
        cp16(s + dstw * 4u, g);
    }
    CP_COMMIT();
}

__device__ __forceinline__ void gemm_compute(const uint32_t* __restrict__ As,
                                             const uint32_t* __restrict__ Bs,
                                             int wm, int wn, int gid, int tig,
                                             float acc[4][4][4]) {
    #pragma unroll
    for (int kk = 0; kk < 2; kk++) {
        const int w = kk * 8 + tig;
        uint32_t bh[4][2], bl[4][2];
        #pragma unroll
        for (int nt = 0; nt < 4; nt++) {
            const uint32_t* br = Bs + (wn * 32 + nt * 8 + gid) * 36;
            bh[nt][0] = br[w];      bh[nt][1] = br[w + 4];
            bl[nt][0] = br[16 + w]; bl[nt][1] = br[16 + w + 4];
        }
        #pragma unroll
        for (int mt = 0; mt < 4; mt++) {
            const int r = wm * 64 + mt * 16 + gid;
            uint32_t ah[4], al[4];
            ah[0] = As[r * 36 + w];            ah[1] = As[(r + 8) * 36 + w];
            ah[2] = As[r * 36 + w + 4];        ah[3] = As[(r + 8) * 36 + w + 4];
            al[0] = As[r * 36 + 16 + w];       al[1] = As[(r + 8) * 36 + 16 + w];
            al[2] = As[r * 36 + 16 + w + 4];   al[3] = As[(r + 8) * 36 + 16 + w + 4];
            #pragma unroll
            for (int nt = 0; nt < 4; nt++) {
                mma16(acc[mt][nt], ah, bh[nt]);
                mma16(acc[mt][nt], ah, bl[nt]);
                mma16(acc[mt][nt], al, bh[nt]);
            }
        }
    }
}

__device__ __forceinline__ void gemm_main(const uint32_t* Ahi, const uint32_t* Alo,
                                          const uint32_t* Bhi, const uint32_t* Blo,
                                          float acc[4][4][4]) {
    extern __shared__ uint32_t dsm[];
    const uint32_t sbase = smem_u32(dsm);

    gemm_stage(sbase, 0, Ahi, Alo, Bhi, Blo, 0);
    gemm_stage(sbase, 1, Ahi, Alo, Bhi, Blo, 32);

    const int tid = threadIdx.x;
    const int wid = tid >> 5, lane = tid & 31;
    const int gid = lane >> 2, tig = lane & 3;
    const int wm = wid & 1, wn = wid >> 1;

    #pragma unroll 1
    for (int kt = 0; kt < 32; kt++) {
        if (kt < 30) asm volatile("cp.async.wait_group 1;" ::: "memory");
        else         asm volatile("cp.async.wait_group 0;" ::: "memory");
        __syncthreads();
        const uint32_t* As = dsm + (kt & 1) * 9216;
        const uint32_t* Bs = As + 4608;
        gemm_compute(As, Bs, wm, wn, gid, tig, acc);
        __syncthreads();
        if (kt + 2 < 32)
            gemm_stage(sbase, kt & 1, Ahi, Alo, Bhi, Blo, (kt + 2) * 32);
    }
}

// ---------------------------------------------------------------------------
// Kernel 0a: split x -> x_hi, x_lo
// ---------------------------------------------------------------------------
__global__ __launch_bounds__(256) void split_x_kernel(const float* __restrict__ x) {
    int i = (blockIdx.x * 256 + threadIdx.x) * 4;
    float4 v = *(const float4*)&x[i];
    uint32_t h0, l0, h1, l1;
    split2(v.x, v.y, h0, l0);
    split2(v.z, v.w, h1, l1);
    *(uint2*)&g_x_hi[i >> 1] = make_uint2(h0, h1);
    *(uint2*)&g_x_lo[i >> 1] = make_uint2(l0, l1);
}

// ---------------------------------------------------------------------------
// Kernel 0b: transpose+split weights  W[k][n] -> w_hi/lo[z][n][k]
// ---------------------------------------------------------------------------
__global__ __launch_bounds__(256) void transpose_split_kernel(
    const float* __restrict__ wq, const float* __restrict__ wk,
    const float* __restrict__ wv, const float* __restrict__ wo)
{
    __shared__ float tile[32][33];
    const float* src = (blockIdx.z == 0) ? wq : (blockIdx.z == 1) ? wk
                       : (blockIdx.z == 2) ? wv : wo;
    __nv_bfloat16* dh = (__nv_bfloat16*)(g_w_hi + (size_t)blockIdx.z * DM * DM / 2);
    __nv_bfloat16* dl = (__nv_bfloat16*)(g_w_lo + (size_t)blockIdx.z * DM * DM / 2);
    int x = blockIdx.x * 32 + threadIdx.x;
    int y0 = blockIdx.y * 32;
    #pragma unroll
    for (int i = threadIdx.y; i < 32; i += 8)
        tile[i][threadIdx.x] = src[(size_t)(y0 + i) * DM + x];
    __syncthreads();
    int xo = blockIdx.y * 32 + threadIdx.x;
    int yo0 = blockIdx.x * 32;
    #pragma unroll
    for (int i = threadIdx.y; i < 32; i += 8) {
        float v = tile[threadIdx.x][i];
        __nv_bfloat16 h = __float2bfloat16(v);
        dh[(size_t)(yo0 + i) * DM + xo] = h;
        dl[(size_t)(yo0 + i) * DM + xo] = __float2bfloat16(v - __bfloat162float(h));
    }
}

// ---------------------------------------------------------------------------
// Kernel 0c: split + transpose V  g_v[bh][t][d] -> g_vt_hi/lo[bh][d][t-pair]
// ---------------------------------------------------------------------------
__global__ __launch_bounds__(256) void split_v_kernel() {
    __shared__ float tile[64][65];
    const int bh = blockIdx.y, tt = blockIdx.x;
    const int tid = threadIdx.x;
    const float* src = g_v + ((size_t)bh * TSEQ + tt * 64) * 64;
    #pragma unroll
    for (int it = 0; it < 4; it++) {
        int lin = it * 256 + tid;
        int t = lin >> 4, d4 = (lin & 15) << 2;
        float4 v = *(const float4*)&src[t * 64 + d4];
        tile[t][d4 + 0] = v.x; tile[t][d4 + 1] = v.y;
        tile[t][d4 + 2] = v.z; tile[t][d4 + 3] = v.w;
    }
    __syncthreads();
    uint32_t* dh = g_vt_hi + (size_t)bh * 64 * (TSEQ / 2) + tt * 32;
    uint32_t* dl = g_vt_lo + (size_t)bh * 64 * (TSEQ / 2) + tt * 32;
    #pragma unroll
    for (int it = 0; it < 8; it++) {
        int lin = it * 256 + tid;
        int d = lin >> 5, tp = lin & 31;
        uint32_t hi, lo;
        split2(tile[2 * tp][d], tile[2 * tp + 1][d], hi, lo);
        dh[(size_t)d * (TSEQ / 2) + tp] = hi;
        dl[(size_t)d * (TSEQ / 2) + tp] = lo;
    }
}

// ---------------------------------------------------------------------------
// Kernel 1: QKV projection. grid (8, 32, 3).
// ---------------------------------------------------------------------------
__global__ __launch_bounds__(256, 2) void qkv_mma_kernel(
    const float* __restrict__ bq, const float* __restrict__ bk,
    const float* __restrict__ bv)
{
    const int z = blockIdx.z;
    const float* bias = (z == 0) ? bq : (z == 1) ? bk : bv;
    const int m0 = blockIdx.y * 128, n0 = blockIdx.x * 128;

    float acc[4][4][4];
    #pragma unroll
    for (int mt = 0; mt < 4; mt++)
        #pragma unroll
        for (int nt = 0; nt < 4; nt++)
            #pragma unroll
            for (int i = 0; i < 4; i++) acc[mt][nt][i] = 0.0f;

    gemm_main(g_x_hi + (size_t)m0 * 512, g_x_lo + (size_t)m0 * 512,
              g_w_hi + (size_t)z * (DM * DM / 2) + (size_t)n0 * 512,
              g_w_lo + (size_t)z * (DM * DM / 2) + (size_t)n0 * 512, acc);

    const int tid = threadIdx.x;
    const int wid = tid >> 5, lane = tid & 31;
    const int gid = lane >> 2, tig = lane & 3;
    const int wm = wid & 1, wn = wid >> 1;

    #pragma unroll
    for (int nt = 0; nt < 4; nt++) {
        int col = n0 + wn * 32 + nt * 8 + 2 * tig;
        int h = col >> 6, d = col & 63;
        float b0 = bias[col], b1 = bias[col + 1];
        #pragma unroll
        for (int mt = 0; mt < 4; mt++) {
            int row = m0 + wm * 64 + mt * 16 + gid;
            int b = row >> 11, t = row & 2047;
            size_t base = ((size_t)(b * NH + h) * TSEQ + t) << 6;
            if (z == 2) {
                *(float2*)&g_v[base + d] =
                    make_float2(acc[mt][nt][0] + b0, acc[mt][nt][1] + b1);
                *(float2*)&g_v[base + 512 + d] =
                    make_float2(acc[mt][nt][2] + b0, acc[mt][nt][3] + b1);
            } else {
                float sc = (z == 0) ? 0.125f : 1.0f;
                uint32_t *ph = (z == 0) ? g_q_hi : g_k_hi;
                uint32_t *pl = (z == 0) ? g_q_lo : g_k_lo;
                uint32_t hi, lo;
                split2((acc[mt][nt][0] + b0) * sc, (acc[mt][nt][1] + b1) * sc, hi, lo);
                ph[(base + d) >> 1] = hi; pl[(base + d) >> 1] = lo;
                split2((acc[mt][nt][2] + b0) * sc, (acc[mt][nt][3] + b1) * sc, hi, lo);
                ph[(base + 512 + d) >> 1] = hi; pl[(base + 512 + d) >> 1] = lo;
            }
        }
    }
}

// ---------------------------------------------------------------------------
// Kernel 3: O projection. grid (8, 32).
// ---------------------------------------------------------------------------
__global__ __launch_bounds__(256, 2) void oproj_mma_kernel(
    const float* __restrict__ bo, float* __restrict__ out)
{
    const int m0 = blockIdx.y * 128, n0 = blockIdx.x * 128;

    float acc[4][4][4];
    #pragma unroll
    for (int mt = 0; mt < 4; mt++)
        #pragma unroll
        for (int nt = 0; nt < 4; nt++)
            #pragma unroll
            for (int i = 0; i < 4; i++) acc[mt][nt][i] = 0.0f;

    gemm_main(g_ao_hi + (size_t)m0 * 512, g_ao_lo + (size_t)m0 * 512,
              g_w_hi + (size_t)3 * (DM * DM / 2) + (size_t)n0 * 512,
              g_w_lo + (size_t)3 * (DM * DM / 2) + (size_t)n0 * 512, acc);

    const int tid = threadIdx.x;
    const int wid = tid >> 5, lane = tid & 31;
    const int gid = lane >> 2, tig = lane & 3;
    const int wm = wid & 1, wn = wid >> 1;

    #pragma unroll
    for (int nt = 0; nt < 4; nt++) {
        int col = n0 + wn * 32 + nt * 8 + 2 * tig;
        float b0 = bo[col], b1 = bo[col + 1];
        #pragma unroll
        for (int mt = 0; mt < 4; mt++) {
            int row = m0 + wm * 64 + mt * 16 + gid;
            *(float2*)&out[(size_t)row * DM + col] =
                make_float2(acc[mt][nt][0] + b0, acc[mt][nt][1] + b1);
            *(float2*)&out[(size_t)(row + 8) * DM + col] =
                make_float2(acc[mt][nt][2] + b0, acc[mt][nt][3] + b1);
        }
    }
}

// ---------------------------------------------------------------------------
// Kernel 2: causal flash attention. 2 q-tiles (15-bx, bx) per block -> uniform
// work, 256 blocks, single wave at 2 CTA/SM. Pure cp.async staging (K and
// pre-split transposed V), Q-lo in smem, Q-hi in regs.
// SMEM words: Qlo[128][36]=4608 | buf0 (K 64x68 + V 64x68)=8704 | buf1 8704
// ---------------------------------------------------------------------------
#define ATT_BUF0 4608
__device__ __forceinline__ void attn_stage(uint32_t sbase, int kt, int buf,
                                           const uint32_t* kh, const uint32_t* kl,
                                           const uint32_t* vh, const uint32_t* vl)
{
    const int tid = threadIdx.x;
    uint32_t kb = sbase + (uint32_t)(ATT_BUF0 + buf * 8704) * 4u;
    uint32_t vb = kb + 4352u * 4u;
    #pragma unroll
    for (int it = 0; it < 8; it++) {
        int lin = it * 256 + tid;
        int isV = lin >> 10;
        int r = (lin >> 4) & 63;
        int c = lin & 15;
        int ishi = (c < 8);
        int cc = c & 7;
        const uint32_t* src;
        uint32_t dst;
        if (!isV) {
            src = (ishi ? kh : kl) + (size_t)(kt * 64 + r) * 32 + cc * 4;
            dst = kb + (uint32_t)(r * 68 + (ishi ? 0 : 32) + cc * 4) * 4u;
        } else {
            src = (ishi ? vh : vl) + (size_t)r * (TSEQ / 2) + kt * 32 + cc * 4;
            dst = vb + (uint32_t)(r * 68 + (ishi ? 0 : 32) + cc * 4) * 4u;
        }
        cp16(dst, src);
    }
    CP_COMMIT();
}

__global__ __launch_bounds__(256, 2) void attn_mma_kernel()
{
    extern __shared__ uint32_t dsm[];
    const uint32_t sbase = smem_u32(dsm);

    const int tid = threadIdx.x;
    const int wid = tid >> 5, lane = tid & 31;
    const int gid = lane >> 2, tig = lane & 3;
    const int bh = blockIdx.y;
    const int b = bh >> 4, h = bh & 15;

    const uint32_t* kh = g_k_hi + (size_t)bh * TSEQ * 32;
    const uint32_t* kl = g_k_lo + (size_t)bh * TSEQ * 32;
    const uint32_t* vh = g_vt_hi + (size_t)bh * 64 * (TSEQ / 2);
    const uint32_t* vl = g_vt_lo + (size_t)bh * 64 * (TSEQ / 2);

    const int r0l = wid * 16 + gid;

    #pragma unroll 1
    for (int pass = 0; pass < 2; pass++) {
        const int qt = (pass == 0) ? (15 - (int)blockIdx.x) : (int)blockIdx.x;
        const uint32_t* qh = g_q_hi + ((size_t)bh * TSEQ + (size_t)qt * 128) * 32;
        const uint32_t* ql = g_q_lo + ((size_t)bh * TSEQ + (size_t)qt * 128) * 32;
        const int nkv = 2 * qt + 2;

        __syncthreads();   // all warps done with buffers/Qlo from prior pass

        // stage Q-lo (cp.async, folds into stage-0's commit group)
        #pragma unroll
        for (int it = 0; it < 4; it++) {
            int lin = it * 256 + tid;
            int r = lin >> 3, cc = lin & 7;
            cp16(sbase + (uint32_t)(r * 36 + cc * 4) * 4u, ql + (size_t)r * 32 + cc * 4);
        }
        attn_stage(sbase, 0, 0, kh, kl, vh, vl);
        attn_stage(sbase, 1, 1, kh, kl, vh, vl);

        // Q-hi fragments in registers
        uint32_t qfh[4][4];
        #pragma unroll
        for (int ks = 0; ks < 4; ks++) {
            int w = ks * 8 + tig;
            qfh[ks][0] = qh[(size_t)r0l * 32 + w];
            qfh[ks][1] = qh[(size_t)(r0l + 8) * 32 + w];
            qfh[ks][2] = qh[(size_t)r0l * 32 + w + 4];
            qfh[ks][3] = qh[(size_t)(r0l + 8) * 32 + w + 4];
        }

        float o[8][4];
        #pragma unroll
        for (int nt = 0; nt < 8; nt++)
            #pragma unroll
            for (int i = 0; i < 4; i++) o[nt][i] = 0.0f;
        float m0 = -1e30f, m1 = -1e30f, l0 = 0.0f, l1 = 0.0f;

        #pragma unroll 1
        for (int kt = 0; kt < nkv; kt++) {
            if (kt + 1 < nkv) asm volatile("cp.async.wait_group 1;" ::: "memory");
            else              asm volatile("cp.async.wait_group 0;" ::: "memory");
            __syncthreads();

            const uint32_t* Ks = dsm + ATT_BUF0 + (kt & 1) * 8704;
            const uint32_t* Vt = Ks + 4352;

            // ---- S = Q @ K^T (3-term bf16; Q-lo fragment from smem) ----
            float s[8][4];
            #pragma unroll
            for (int nt = 0; nt < 8; nt++)
                #pragma unroll
                for (int i = 0; i < 4; i++) s[nt][i] = 0.0f;
            #pragma unroll
            for (int ks = 0; ks < 4; ks++) {
                int w = ks * 8 + tig;
                uint32_t qflr[4];
                qflr[0] = dsm[r0l * 36 + w];
                qflr[1] = dsm[(r0l + 8) * 36 + w];
                qflr[2] = dsm[r0l * 36 + w + 4];
                qflr[3] = dsm[(r0l + 8) * 36 + w + 4];
                #pragma unroll
                for (int nt = 0; nt < 8; nt++) {
                    const uint32_t* kr = Ks + (nt * 8 + gid) * 68;
                    uint32_t bh2[2] = { kr[w], kr[w + 4] };
                    uint32_t bl2[2] = { kr[32 + w], kr[32 + w + 4] };
                    mma16(s[nt], qfh[ks], bh2);
                    mma16(s[nt], qfh[ks], bl2);
                    mma16(s[nt], qflr, bh2);
                }
            }

            // ---- causal mask (near-diagonal tiles only) ----
            if (kt >= 2 * qt) {
                int row0 = qt * 128 + r0l;
                #pragma unroll
                for (int nt = 0; nt < 8; nt++) {
                    int c0 = kt * 64 + nt * 8 + 2 * tig;
                    if (c0 > row0)         s[nt][0] = -1e30f;
                    if (c0 + 1 > row0)     s[nt][1] = -1e30f;
                    if (c0 > row0 + 8)     s[nt][2] = -1e30f;
                    if (c0 + 1 > row0 + 8) s[nt][3] = -1e30f;
                }
            }

            // ---- online softmax ----
            {
                float rm0 = -1e30f, rm1 = -1e30f;
                #pragma unroll
                for (int nt = 0; nt < 8; nt++) {
                    rm0 = fmaxf(rm0, fmaxf(s[nt][0], s[nt][1]));
                    rm1 = fmaxf(rm1, fmaxf(s[nt][2], s[nt][3]));
                }
                #pragma unroll
                for (int off = 1; off <= 2; off <<= 1) {
                    rm0 = fmaxf(rm0, __shfl_xor_sync(0xffffffffu, rm0, off, 4));
                    rm1 = fmaxf(rm1, __shfl_xor_sync(0xffffffffu, rm1, off, 4));
                }
                float mn0 = fmaxf(m0, rm0), mn1 = fmaxf(m1, rm1);
                float cr0 = __expf(m0 - mn0), cr1 = __expf(m1 - mn1);
                m0 = mn0; m1 = mn1;
                float rs0 = 0.0f, rs1 = 0.0f;
                #pragma unroll
                for (int nt = 0; nt < 8; nt++) {
                    s[nt][0] = __expf(s[nt][0] - mn0);
                    s[nt][1] = __expf(s[nt][1] - mn0);
                    s[nt][2] = __expf(s[nt][2] - mn1);
                    s[nt][3] = __expf(s[nt][3] - mn1);
                    rs0 += s[nt][0] + s[nt][1];
                    rs1 += s[nt][2] + s[nt][3];
                }
                #pragma unroll
                for (int off = 1; off <= 2; off <<= 1) {
                    rs0 += __shfl_xor_sync(0xffffffffu, rs0, off, 4);
                    rs1 += __shfl_xor_sync(0xffffffffu, rs1, off, 4);
                }
                l0 = l0 * cr0 + rs0;
                l1 = l1 * cr1 + rs1;
                #pragma unroll
                for (int nt = 0; nt < 8; nt++) {
                    o[nt][0] *= cr0; o[nt][1] *= cr0;
                    o[nt][2] *= cr1; o[nt][3] *= cr1;
                }
            }

            // ---- O += P @ V (P register-resident, split to hi/lo) ----
            #pragma unroll
            for (int ks = 0; ks < 4; ks++) {
                uint32_t ph[4], pl[4];
                split2(s[2*ks][0],   s[2*ks][1],   ph[0], pl[0]);
                split2(s[2*ks][2],   s[2*ks][3],   ph[1], pl[1]);
                split2(s[2*ks+1][0], s[2*ks+1][1], ph[2], pl[2]);
                split2(s[2*ks+1][2], s[2*ks+1][3], ph[3], pl[3]);
                int w = ks * 8 + tig;
                #pragma unroll
                for (int nt = 0; nt < 8; nt++) {
                    const uint32_t* vr = Vt + (nt * 8 + gid) * 68;
                    uint32_t bh2[2] = { vr[w], vr[w + 4] };
                    uint32_t bl2[2] = { vr[32 + w], vr[32 + w + 4] };
                    mma16(o[nt], ph, bh2);
                    mma16(o[nt], ph, bl2);
                    mma16(o[nt], pl, bh2);
                }
            }

            __syncthreads();
            if (kt + 2 < nkv) attn_stage(sbase, kt + 2, kt & 1, kh, kl, vh, vl);
        }

        // ---- epilogue: normalize, split, write g_ao_hi/lo [B,T,H*Dh] ----
        const float inv0 = 1.0f / l0, inv1 = 1.0f / l1;
        size_t row0 = (size_t)(b * TSEQ + qt * 128 + r0l);
        #pragma unroll
        for (int nt = 0; nt < 8; nt++) {
            int c = nt * 8 + 2 * tig;
            uint32_t hi, lo;
            split2(o[nt][0] * inv0, o[nt][1] * inv0, hi, lo);
            g_ao_hi[(row0 * DM + h * 64 + c) >> 1] = hi;
            g_ao_lo[(row0 * DM + h * 64 + c) >> 1] = lo;
            split2(o[nt][2] * inv1, o[nt][3] * inv1, hi, lo);
            g_ao_hi[((row0 + 8) * DM + h * 64 + c) >> 1] = hi;
            g_ao_lo[((row0 + 8) * DM + h * 64 + c) >> 1] = lo;
        }
    }
}

// ---------------------------------------------------------------------------
extern "C" void kernel_launch(void* const* d_in, const int* in_sizes, int n_in,
                              void* d_out, int out_size)
{
    const float* x  = (const float*)d_in[0];
    const float* wq = (const float*)d_in[1];
    const float* bq = (const float*)d_in[2];
    const float* wk = (const float*)d_in[3];
    const float* bk = (const float*)d_in[4];
    const float* wv = (const float*)d_in[5];
    const float* bv = (const float*)d_in[6];
    const float* wo = (const float*)d_in[7];
    const float* bo = (const float*)d_in[8];
    float* out = (float*)d_out;

    static const int GEMM_SMEM = 73728;                        // 2 stages
    static const int ATTN_SMEM = (4608 + 2 * 8704) * 4;        // 88064

    cudaFuncSetAttribute(qkv_mma_kernel,
                         cudaFuncAttributeMaxDynamicSharedMemorySize, GEMM_SMEM);
    cudaFuncSetAttribute(oproj_mma_kernel,
                         cudaFuncAttributeMaxDynamicSharedMemorySize, GEMM_SMEM);
    cudaFuncSetAttribute(attn_mma_kernel,
                         cudaFuncAttributeMaxDynamicSharedMemorySize, ATTN_SMEM);

    split_x_kernel<<<BT * DM / 1024, 256>>>(x);
    transpose_split_kernel<<<dim3(32, 32, 4), dim3(32, 8)>>>(wq, wk, wv, wo);

    qkv_mma_kernel<<<dim3(8, 32, 3), 256, GEMM_SMEM>>>(bq, bk, bv);

    split_v_kernel<<<dim3(TSEQ / 64, BSZ * NH), 256>>>();

    attn_mma_kernel<<<dim3(8, BSZ * NH), 256, ATTN_SMEM>>>();

    oproj_mma_kernel<<<dim3(8, 32), 256, GEMM_SMEM>>>(bo, out);
}

// round 6
// speedup vs baseline: 2.7877x; 1.0518x over previous
#include <cuda_runtime.h>
#include <cuda_bf16.h>
#include <cstdint>

#define DM   1024
#define NH   16
#define DH   64
#define TSEQ 2048
#define BSZ  2
#define BT   (BSZ*TSEQ)

// ---------------------------------------------------------------------------
// Scratch (static device globals — no allocation). hi/lo bf16 stored as words.
// ---------------------------------------------------------------------------
__device__ __align__(16) uint32_t g_x_hi[BT*DM/2],  g_x_lo[BT*DM/2];
__device__ __align__(16) uint32_t g_w_hi[4*DM*DM/2], g_w_lo[4*DM*DM/2]; // [z][N][K]
__device__ __align__(16) uint32_t g_q_hi[BSZ*NH*TSEQ*DH/2], g_q_lo[BSZ*NH*TSEQ*DH/2];
__device__ __align__(16) uint32_t g_k_hi[BSZ*NH*TSEQ*DH/2], g_k_lo[BSZ*NH*TSEQ*DH/2];
__device__ __align__(16) float    g_v[BSZ*NH*TSEQ*DH];
__device__ __align__(16) uint32_t g_vt_hi[BSZ*NH*DH*(TSEQ/2)], g_vt_lo[BSZ*NH*DH*(TSEQ/2)];
__device__ __align__(16) uint32_t g_ao_hi[BT*DM/2], g_ao_lo[BT*DM/2];

// ---------------------------------------------------------------------------
// helpers
// ---------------------------------------------------------------------------
__device__ __forceinline__ uint32_t smem_u32(const void* p) {
    uint32_t a;
    asm("{ .reg .u64 t; cvta.to.shared.u64 t, %1; cvt.u32.u64 %0, t; }"
        : "=r"(a) : "l"(p));
    return a;
}

__device__ __forceinline__ uint32_t pack2(float e0, float e1) {
    uint32_t r;
    asm("cvt.rn.bf16x2.f32 %0, %1, %2;" : "=r"(r) : "f"(e1), "f"(e0));
    return r;
}

__device__ __forceinline__ void split2(float x0, float x1, uint32_t& hi, uint32_t& lo) {
    hi = pack2(x0, x1);
    float h0 = __uint_as_float(hi << 16);
    float h1 = __uint_as_float(hi & 0xffff0000u);
    lo = pack2(x0 - h0, x1 - h1);
}

__device__ __forceinline__ void mma16(float* d, const uint32_t* a, const uint32_t* b) {
    asm volatile(
        "mma.sync.aligned.m16n8k16.row.col.f32.bf16.bf16.f32 "
        "{%0,%1,%2,%3}, {%4,%5,%6,%7}, {%8,%9}, {%0,%1,%2,%3};"
        : "+f"(d[0]), "+f"(d[1]), "+f"(d[2]), "+f"(d[3])
        : "r"(a[0]), "r"(a[1]), "r"(a[2]), "r"(a[3]), "r"(b[0]), "r"(b[1]));
}

__device__ __forceinline__ void ldsm4(uint32_t* r, uint32_t a) {
    asm volatile("ldmatrix.sync.aligned.m8n8.x4.shared.b16 {%0,%1,%2,%3}, [%4];"
                 : "=r"(r[0]), "=r"(r[1]), "=r"(r[2]), "=r"(r[3]) : "r"(a));
}

__device__ __forceinline__ void cp16(uint32_t saddr, const void* g) {
    asm volatile("cp.async.cg.shared.global [%0], [%1], 16;"
                 :: "r"(saddr), "l"(g) : "memory");
}
#define CP_COMMIT() asm volatile("cp.async.commit_group;" ::: "memory")

// ---------------------------------------------------------------------------
// GEMM: C[128x128] = A[128,1024] @ B[128,1024]^T, both K-major bf16 hi/lo.
// SMEM row: 16 words hi | 16 words lo | 4 pad (stride 36 words).
// 8 warps: 2(M)x4(N), warp tile 64x32. 3-term bf16 MMA, ldmatrix frags.
// ---------------------------------------------------------------------------
__device__ __forceinline__ void gemm_stage(uint32_t sbase, int buf,
                                           const uint32_t* Ahi, const uint32_t* Alo,
                                           const uint32_t* Bhi, const uint32_t* Blo,
                                           int k0) {
    const int tid = threadIdx.x;
    const uint32_t s = sbase + (uint32_t)buf * 36864u;
    #pragma unroll
    for (int it = 0; it < 8; it++) {
        int lin = it * 256 + tid;
        int isB = lin >> 10;
        int r   = (lin >> 3) & 127;
        int c   = lin & 7;
        int ishi = (c < 4);
        int cc  = c & 3;
        const uint32_t* src = isB ? (ishi ? Bhi : Blo) : (ishi ? Ahi : Alo);
        const uint32_t* g = src + (size_t)r * 512 + (k0 >> 1) + cc * 4;
        uint32_t dstw = (uint32_t)(isB * 4608 + r * 36 + (ishi ? 0 : 16) + cc * 4);
        cp16(s + dstw * 4u, g);
    }
    CP_COMMIT();
}

// A0/B0: per-lane ldmatrix base byte-addresses into the current buffers.
__device__ __forceinline__ void gemm_compute(uint32_t A0, uint32_t B0,
                                             float acc[4][4][4]) {
    #pragma unroll
    for (int kk = 0; kk < 2; kk++) {
        uint32_t b01h[4], b01l[4], b23h[4], b23l[4];
        ldsm4(b01h, B0 + kk * 32);
        ldsm4(b01l, B0 + kk * 32 + 64);
        ldsm4(b23h, B0 + 2304 + kk * 32);
        ldsm4(b23l, B0 + 2304 + kk * 32 + 64);
        #pragma unroll
        for (int mt = 0; mt < 4; mt++) {
            uint32_t ah[4], al[4];
            ldsm4(ah, A0 + mt * 2304 + kk * 32);
            ldsm4(al, A0 + mt * 2304 + kk * 32 + 64);
            mma16(acc[mt][0], ah, b01h);     mma16(acc[mt][0], ah, b01l);
            mma16(acc[mt][0], al, b01h);
            mma16(acc[mt][1], ah, b01h + 2); mma16(acc[mt][1], ah, b01l + 2);
            mma16(acc[mt][1], al, b01h + 2);
            mma16(acc[mt][2], ah, b23h);     mma16(acc[mt][2], ah, b23l);
            mma16(acc[mt][2], al, b23h);
            mma16(acc[mt][3], ah, b23h + 2); mma16(acc[mt][3], ah, b23l + 2);
            mma16(acc[mt][3], al, b23h + 2);
        }
    }
}

__device__ __forceinline__ void gemm_main(const uint32_t* Ahi, const uint32_t* Alo,
                                          const uint32_t* Bhi, const uint32_t* Blo,
                                          float acc[4][4][4]) {
    extern __shared__ uint32_t dsm[];
    const uint32_t sbase = smem_u32(dsm);

    gemm_stage(sbase, 0, Ahi, Alo, Bhi, Blo, 0);
    gemm_stage(sbase, 1, Ahi, Alo, Bhi, Blo, 32);

    const int tid = threadIdx.x;
    const int wid = tid >> 5, lane = tid & 31;
    const int wm = wid & 1, wn = wid >> 1;

    // ldmatrix per-lane base offsets (bytes)
    const uint32_t aoff =
        (uint32_t)(((wm * 64 + (lane & 15)) * 36 + ((lane & 16) ? 4 : 0)) * 4);
    const uint32_t boff =
        (uint32_t)(((wn * 32 + (lane & 7) + ((lane & 16) >> 1)) * 36
                    + ((lane & 8) ? 4 : 0)) * 4);

    #pragma unroll 1
    for (int kt = 0; kt < 32; kt++) {
        if (kt < 30) asm volatile("cp.async.wait_group 1;" ::: "memory");
        else         asm volatile("cp.async.wait_group 0;" ::: "memory");
        __syncthreads();
        uint32_t base = sbase + (uint32_t)(kt & 1) * 36864u;
        gemm_compute(base + aoff, base + 18432u + boff, acc);
        __syncthreads();
        if (kt + 2 < 32)
            gemm_stage(sbase, kt & 1, Ahi, Alo, Bhi, Blo, (kt + 2) * 32);
    }
}

// ---------------------------------------------------------------------------
// Kernel 0a: split x -> x_hi, x_lo
// ---------------------------------------------------------------------------
__global__ __launch_bounds__(256) void split_x_kernel(const float* __restrict__ x) {
    int i = (blockIdx.x * 256 + threadIdx.x) * 4;
    float4 v = *(const float4*)&x[i];
    uint32_t h0, l0, h1, l1;
    split2(v.x, v.y, h0, l0);
    split2(v.z, v.w, h1, l1);
    *(uint2*)&g_x_hi[i >> 1] = make_uint2(h0, h1);
    *(uint2*)&g_x_lo[i >> 1] = make_uint2(l0, l1);
}

// ---------------------------------------------------------------------------
// Kernel 0b: transpose+split weights  W[k][n] -> w_hi/lo[z][n][k]
// ---------------------------------------------------------------------------
__global__ __launch_bounds__(256) void transpose_split_kernel(
    const float* __restrict__ wq, const float* __restrict__ wk,
    const float* __restrict__ wv, const float* __restrict__ wo)
{
    __shared__ float tile[32][33];
    const float* src = (blockIdx.z == 0) ? wq : (blockIdx.z == 1) ? wk
                       : (blockIdx.z == 2) ? wv : wo;
    __nv_bfloat16* dh = (__nv_bfloat16*)(g_w_hi + (size_t)blockIdx.z * DM * DM / 2);
    __nv_bfloat16* dl = (__nv_bfloat16*)(g_w_lo + (size_t)blockIdx.z * DM * DM / 2);
    int x = blockIdx.x * 32 + threadIdx.x;
    int y0 = blockIdx.y * 32;
    #pragma unroll
    for (int i = threadIdx.y; i < 32; i += 8)
        tile[i][threadIdx.x] = src[(size_t)(y0 + i) * DM + x];
    __syncthreads();
    int xo = blockIdx.y * 32 + threadIdx.x;
    int yo0 = blockIdx.x * 32;
    #pragma unroll
    for (int i = threadIdx.y; i < 32; i += 8) {
        float v = tile[threadIdx.x][i];
        __nv_bfloat16 h = __float2bfloat16(v);
        dh[(size_t)(yo0 + i) * DM + xo] = h;
        dl[(size_t)(yo0 + i) * DM + xo] = __float2bfloat16(v - __bfloat162float(h));
    }
}

// ---------------------------------------------------------------------------
// Kernel 0c: split + transpose V  g_v[bh][t][d] -> g_vt_hi/lo[bh][d][t-pair]
// ---------------------------------------------------------------------------
__global__ __launch_bounds__(256) void split_v_kernel() {
    __shared__ float tile[64][65];
    const int bh = blockIdx.y, tt = blockIdx.x;
    const int tid = threadIdx.x;
    const float* src = g_v + ((size_t)bh * TSEQ + tt * 64) * 64;
    #pragma unroll
    for (int it = 0; it < 4; it++) {
        int lin = it * 256 + tid;
        int t = lin >> 4, d4 = (lin & 15) << 2;
        float4 v = *(const float4*)&src[t * 64 + d4];
        tile[t][d4 + 0] = v.x; tile[t][d4 + 1] = v.y;
        tile[t][d4 + 2] = v.z; tile[t][d4 + 3] = v.w;
    }
    __syncthreads();
    uint32_t* dh = g_vt_hi + (size_t)bh * 64 * (TSEQ / 2) + tt * 32;
    uint32_t* dl = g_vt_lo + (size_t)bh * 64 * (TSEQ / 2) + tt * 32;
    #pragma unroll
    for (int it = 0; it < 8; it++) {
        int lin = it * 256 + tid;
        int d = lin >> 5, tp = lin & 31;
        uint32_t hi, lo;
        split2(tile[2 * tp][d], tile[2 * tp + 1][d], hi, lo);
        dh[(size_t)d * (TSEQ / 2) + tp] = hi;
        dl[(size_t)d * (TSEQ / 2) + tp] = lo;
    }
}

// ---------------------------------------------------------------------------
// Kernel 1: QKV projection. grid (8, 32, 3).
// ---------------------------------------------------------------------------
__global__ __launch_bounds__(256, 2) void qkv_mma_kernel(
    const float* __restrict__ bq, const float* __restrict__ bk,
    const float* __restrict__ bv)
{
    const int z = blockIdx.z;
    const float* bias = (z == 0) ? bq : (z == 1) ? bk : bv;
    const int m0 = blockIdx.y * 128, n0 = blockIdx.x * 128;

    float acc[4][4][4];
    #pragma unroll
    for (int mt = 0; mt < 4; mt++)
        #pragma unroll
        for (int nt = 0; nt < 4; nt++)
            #pragma unroll
            for (int i = 0; i < 4; i++) acc[mt][nt][i] = 0.0f;

    gemm_main(g_x_hi + (size_t)m0 * 512, g_x_lo + (size_t)m0 * 512,
              g_w_hi + (size_t)z * (DM * DM / 2) + (size_t)n0 * 512,
              g_w_lo + (size_t)z * (DM * DM / 2) + (size_t)n0 * 512, acc);

    const int tid = threadIdx.x;
    const int wid = tid >> 5, lane = tid & 31;
    const int gid = lane >> 2, tig = lane & 3;
    const int wm = wid & 1, wn = wid >> 1;

    #pragma unroll
    for (int nt = 0; nt < 4; nt++) {
        int col = n0 + wn * 32 + nt * 8 + 2 * tig;
        int h = col >> 6, d = col & 63;
        float b0 = bias[col], b1 = bias[col + 1];
        #pragma unroll
        for (int mt = 0; mt < 4; mt++) {
            int row = m0 + wm * 64 + mt * 16 + gid;
            int b = row >> 11, t = row & 2047;
            size_t base = ((size_t)(b * NH + h) * TSEQ + t) << 6;
            if (z == 2) {
                *(float2*)&g_v[base + d] =
                    make_float2(acc[mt][nt][0] + b0, acc[mt][nt][1] + b1);
                *(float2*)&g_v[base + 512 + d] =
                    make_float2(acc[mt][nt][2] + b0, acc[mt][nt][3] + b1);
            } else {
                float sc = (z == 0) ? 0.125f : 1.0f;
                uint32_t *ph = (z == 0) ? g_q_hi : g_k_hi;
                uint32_t *pl = (z == 0) ? g_q_lo : g_k_lo;
                uint32_t hi, lo;
                split2((acc[mt][nt][0] + b0) * sc, (acc[mt][nt][1] + b1) * sc, hi, lo);
                ph[(base + d) >> 1] = hi; pl[(base + d) >> 1] = lo;
                split2((acc[mt][nt][2] + b0) * sc, (acc[mt][nt][3] + b1) * sc, hi, lo);
                ph[(base + 512 + d) >> 1] = hi; pl[(base + 512 + d) >> 1] = lo;
            }
        }
    }
}

// ---------------------------------------------------------------------------
// Kernel 3: O projection. grid (8, 32).
// ---------------------------------------------------------------------------
__global__ __launch_bounds__(256, 2) void oproj_mma_kernel(
    const float* __restrict__ bo, float* __restrict__ out)
{
    const int m0 = blockIdx.y * 128, n0 = blockIdx.x * 128;

    float acc[4][4][4];
    #pragma unroll
    for (int mt = 0; mt < 4; mt++)
        #pragma unroll
        for (int nt = 0; nt < 4; nt++)
            #pragma unroll
            for (int i = 0; i < 4; i++) acc[mt][nt][i] = 0.0f;

    gemm_main(g_ao_hi + (size_t)m0 * 512, g_ao_lo + (size_t)m0 * 512,
              g_w_hi + (size_t)3 * (DM * DM / 2) + (size_t)n0 * 512,
              g_w_lo + (size_t)3 * (DM * DM / 2) + (size_t)n0 * 512, acc);

    const int tid = threadIdx.x;
    const int wid = tid >> 5, lane = tid & 31;
    const int gid = lane >> 2, tig = lane & 3;
    const int wm = wid & 1, wn = wid >> 1;

    #pragma unroll
    for (int nt = 0; nt < 4; nt++) {
        int col = n0 + wn * 32 + nt * 8 + 2 * tig;
        float b0 = bo[col], b1 = bo[col + 1];
        #pragma unroll
        for (int mt = 0; mt < 4; mt++) {
            int row = m0 + wm * 64 + mt * 16 + gid;
            *(float2*)&out[(size_t)row * DM + col] =
                make_float2(acc[mt][nt][0] + b0, acc[mt][nt][1] + b1);
            *(float2*)&out[(size_t)(row + 8) * DM + col] =
                make_float2(acc[mt][nt][2] + b0, acc[mt][nt][3] + b1);
        }
    }
}

// ---------------------------------------------------------------------------
// Kernel 2: causal flash attention, ldmatrix fragment loads.
// SMEM words: Qlo[128][36]=4608 | buf0 (K 64x68 + V 64x68)=8704 | buf1 8704
// ---------------------------------------------------------------------------
#define ATT_BUF0 4608
__device__ __forceinline__ void attn_stage(uint32_t sbase, int kt, int buf,
                                           const uint32_t* kh, const uint32_t* kl,
                                           const uint32_t* vh, const uint32_t* vl)
{
    const int tid = threadIdx.x;
    uint32_t kb = sbase + (uint32_t)(ATT_BUF0 + buf * 8704) * 4u;
    uint32_t vb = kb + 4352u * 4u;
    #pragma unroll
    for (int it = 0; it < 8; it++) {
        int lin = it * 256 + tid;
        int isV = lin >> 10;
        int r = (lin >> 4) & 63;
        int c = lin & 15;
        int ishi = (c < 8);
        int cc = c & 7;
        const uint32_t* src;
        uint32_t dst;
        if (!isV) {
            src = (ishi ? kh : kl) + (size_t)(kt * 64 + r) * 32 + cc * 4;
            dst = kb + (uint32_t)(r * 68 + (ishi ? 0 : 32) + cc * 4) * 4u;
        } else {
            src = (ishi ? vh : vl) + (size_t)r * (TSEQ / 2) + kt * 32 + cc * 4;
            dst = vb + (uint32_t)(r * 68 + (ishi ? 0 : 32) + cc * 4) * 4u;
        }
        cp16(dst, src);
    }
    CP_COMMIT();
}

__global__ __launch_bounds__(256, 2) void attn_mma_kernel()
{
    extern __shared__ uint32_t dsm[];
    const uint32_t sbase = smem_u32(dsm);

    const int tid = threadIdx.x;
    const int wid = tid >> 5, lane = tid & 31;
    const int gid = lane >> 2, tig = lane & 3;
    const int bh = blockIdx.y;
    const int b = bh >> 4, h = bh & 15;

    const uint32_t* kh = g_k_hi + (size_t)bh * TSEQ * 32;
    const uint32_t* kl = g_k_lo + (size_t)bh * TSEQ * 32;
    const uint32_t* vh = g_vt_hi + (size_t)bh * 64 * (TSEQ / 2);
    const uint32_t* vl = g_vt_lo + (size_t)bh * 64 * (TSEQ / 2);

    const int r0l = wid * 16 + gid;

    // per-lane ldmatrix base offsets (bytes)
    const uint32_t qoff =
        (uint32_t)(((wid * 16 + (lane & 15)) * 36 + ((lane & 16) ? 4 : 0)) * 4);
    const uint32_t kvoff =
        (uint32_t)((((lane & 7) + ((lane & 16) >> 1)) * 68
                    + ((lane & 8) ? 4 : 0)) * 4);

    #pragma unroll 1
    for (int pass = 0; pass < 2; pass++) {
        const int qt = (pass == 0) ? (15 - (int)blockIdx.x) : (int)blockIdx.x;
        const uint32_t* qh = g_q_hi + ((size_t)bh * TSEQ + (size_t)qt * 128) * 32;
        const uint32_t* ql = g_q_lo + ((size_t)bh * TSEQ + (size_t)qt * 128) * 32;
        const int nkv = 2 * qt + 2;

        __syncthreads();   // all warps done with buffers/Qlo from prior pass

        // stage Q-lo (cp.async, folds into stage-0's commit group)
        #pragma unroll
        for (int it = 0; it < 4; it++) {
            int lin = it * 256 + tid;
            int r = lin >> 3, cc = lin & 7;
            cp16(sbase + (uint32_t)(r * 36 + cc * 4) * 4u, ql + (size_t)r * 32 + cc * 4);
        }
        attn_stage(sbase, 0, 0, kh, kl, vh, vl);
        attn_stage(sbase, 1, 1, kh, kl, vh, vl);

        // Q-hi fragments in registers
        uint32_t qfh[4][4];
        #pragma unroll
        for (int ks = 0; ks < 4; ks++) {
            int w = ks * 8 + tig;
            qfh[ks][0] = qh[(size_t)r0l * 32 + w];
            qfh[ks][1] = qh[(size_t)(r0l + 8) * 32 + w];
            qfh[ks][2] = qh[(size_t)r0l * 32 + w + 4];
            qfh[ks][3] = qh[(size_t)(r0l + 8) * 32 + w + 4];
        }

        float o[8][4];
        #pragma unroll
        for (int nt = 0; nt < 8; nt++)
            #pragma unroll
            for (int i = 0; i < 4; i++) o[nt][i] = 0.0f;
        float m0 = -1e30f, m1 = -1e30f, l0 = 0.0f, l1 = 0.0f;

        #pragma unroll 1
        for (int kt = 0; kt < nkv; kt++) {
            if (kt + 1 < nkv) asm volatile("cp.async.wait_group 1;" ::: "memory");
            else              asm volatile("cp.async.wait_group 0;" ::: "memory");
            __syncthreads();

            const uint32_t Kb = sbase + (uint32_t)(ATT_BUF0 + (kt & 1) * 8704) * 4u
                                + kvoff;
            const uint32_t Vb = Kb + 4352u * 4u;

            // ---- S = Q @ K^T (3-term bf16, ldmatrix frags) ----
            float s[8][4];
            #pragma unroll
            for (int nt = 0; nt < 8; nt++)
                #pragma unroll
                for (int i = 0; i < 4; i++) s[nt][i] = 0.0f;
            #pragma unroll
            for (int ks = 0; ks < 4; ks++) {
                uint32_t qflr[4];
                ldsm4(qflr, sbase + qoff + ks * 32);
                #pragma unroll
                for (int ntp = 0; ntp < 4; ntp++) {
                    uint32_t kh4[4], kl4[4];
                    ldsm4(kh4, Kb + ntp * 4352 + ks * 32);
                    ldsm4(kl4, Kb + ntp * 4352 + ks * 32 + 128);
                    mma16(s[2*ntp],   qfh[ks], kh4);
                    mma16(s[2*ntp],   qfh[ks], kl4);
                    mma16(s[2*ntp],   qflr,    kh4);
                    mma16(s[2*ntp+1], qfh[ks], kh4 + 2);
                    mma16(s[2*ntp+1], qfh[ks], kl4 + 2);
                    mma16(s[2*ntp+1], qflr,    kh4 + 2);
                }
            }

            // ---- causal mask (near-diagonal tiles only) ----
            if (kt >= 2 * qt) {
                int row0 = qt * 128 + r0l;
                #pragma unroll
                for (int nt = 0; nt < 8; nt++) {
                    int c0 = kt * 64 + nt * 8 + 2 * tig;
                    if (c0 > row0)         s[nt][0] = -1e30f;
                    if (c0 + 1 > row0)     s[nt][1] = -1e30f;
                    if (c0 > row0 + 8)     s[nt][2] = -1e30f;
                    if (c0 + 1 > row0 + 8) s[nt][3] = -1e30f;
                }
            }

            // ---- online softmax ----
            {
                float rm0 = -1e30f, rm1 = -1e30f;
                #pragma unroll
                for (int nt = 0; nt < 8; nt++) {
                    rm0 = fmaxf(rm0, fmaxf(s[nt][0], s[nt][1]));
                    rm1 = fmaxf(rm1, fmaxf(s[nt][2], s[nt][3]));
                }
                #pragma unroll
                for (int off = 1; off <= 2; off <<= 1) {
                    rm0 = fmaxf(rm0, __shfl_xor_sync(0xffffffffu, rm0, off, 4));
                    rm1 = fmaxf(rm1, __shfl_xor_sync(0xffffffffu, rm1, off, 4));
                }
                float mn0 = fmaxf(m0, rm0), mn1 = fmaxf(m1, rm1);
                float cr0 = __expf(m0 - mn0), cr1 = __expf(m1 - mn1);
                m0 = mn0; m1 = mn1;
                float rs0 = 0.0f, rs1 = 0.0f;
                #pragma unroll
                for (int nt = 0; nt < 8; nt++) {
                    s[nt][0] = __expf(s[nt][0] - mn0);
                    s[nt][1] = __expf(s[nt][1] - mn0);
                    s[nt][2] = __expf(s[nt][2] - mn1);
                    s[nt][3] = __expf(s[nt][3] - mn1);
                    rs0 += s[nt][0] + s[nt][1];
                    rs1 += s[nt][2] + s[nt][3];
                }
                #pragma unroll
                for (int off = 1; off <= 2; off <<= 1) {
                    rs0 += __shfl_xor_sync(0xffffffffu, rs0, off, 4);
                    rs1 += __shfl_xor_sync(0xffffffffu, rs1, off, 4);
                }
                l0 = l0 * cr0 + rs0;
                l1 = l1 * cr1 + rs1;
                #pragma unroll
                for (int nt = 0; nt < 8; nt++) {
                    o[nt][0] *= cr0; o[nt][1] *= cr0;
                    o[nt][2] *= cr1; o[nt][3] *= cr1;
                }
            }

            // ---- O += P @ V (P register-resident, ldmatrix V frags) ----
            #pragma unroll
            for (int ks = 0; ks < 4; ks++) {
                uint32_t ph[4], pl[4];
                split2(s[2*ks][0],   s[2*ks][1],   ph[0], pl[0]);
                split2(s[2*ks][2],   s[2*ks][3],   ph[1], pl[1]);
                split2(s[2*ks+1][0], s[2*ks+1][1], ph[2], pl[2]);
                split2(s[2*ks+1][2], s[2*ks+1][3], ph[3], pl[3]);
                #pragma unroll
                for (int ntp = 0; ntp < 4; ntp++) {
                    uint32_t vh4[4], vl4[4];
                    ldsm4(vh4, Vb + ntp * 4352 + ks * 32);
                    ldsm4(vl4, Vb + ntp * 4352 + ks * 32 + 128);
                    mma16(o[2*ntp],   ph, vh4);
                    mma16(o[2*ntp],   ph, vl4);
                    mma16(o[2*ntp],   pl, vh4);
                    mma16(o[2*ntp+1], ph, vh4 + 2);
                    mma16(o[2*ntp+1], ph, vl4 + 2);
                    mma16(o[2*ntp+1], pl, vh4 + 2);
                }
            }

            __syncthreads();
            if (kt + 2 < nkv) attn_stage(sbase, kt + 2, kt & 1, kh, kl, vh, vl);
        }

        // ---- epilogue: normalize, split, write g_ao_hi/lo [B,T,H*Dh] ----
        const float inv0 = 1.0f / l0, inv1 = 1.0f / l1;
        size_t row0 = (size_t)(b * TSEQ + qt * 128 + r0l);
        #pragma unroll
        for (int nt = 0; nt < 8; nt++) {
            int c = nt * 8 + 2 * tig;
            uint32_t hi, lo;
            split2(o[nt][0] * inv0, o[nt][1] * inv0, hi, lo);
            g_ao_hi[(row0 * DM + h * 64 + c) >> 1] = hi;
            g_ao_lo[(row0 * DM + h * 64 + c) >> 1] = lo;
            split2(o[nt][2] * inv1, o[nt][3] * inv1, hi, lo);
            g_ao_hi[((row0 + 8) * DM + h * 64 + c) >> 1] = hi;
            g_ao_lo[((row0 + 8) * DM + h * 64 + c) >> 1] = lo;
        }
    }
}

// ---------------------------------------------------------------------------
extern "C" void kernel_launch(void* const* d_in, const int* in_sizes, int n_in,
                              void* d_out, int out_size)
{
    const float* x  = (const float*)d_in[0];
    const float* wq = (const float*)d_in[1];
    const float* bq = (const float*)d_in[2];
    const float* wk = (const float*)d_in[3];
    const float* bk = (const float*)d_in[4];
    const float* wv = (const float*)d_in[5];
    const float* bv = (const float*)d_in[6];
    const float* wo = (const float*)d_in[7];
    const float* bo = (const float*)d_in[8];
    float* out = (float*)d_out;

    static const int GEMM_SMEM = 73728;                        // 2 stages
    static const int ATTN_SMEM = (4608 + 2 * 8704) * 4;        // 88064

    cudaFuncSetAttribute(qkv_mma_kernel,
                         cudaFuncAttributeMaxDynamicSharedMemorySize, GEMM_SMEM);
    cudaFuncSetAttribute(oproj_mma_kernel,
                         cudaFuncAttributeMaxDynamicSharedMemorySize, GEMM_SMEM);
    cudaFuncSetAttribute(attn_mma_kernel,
                         cudaFuncAttributeMaxDynamicSharedMemorySize, ATTN_SMEM);

    split_x_kernel<<<BT * DM / 1024, 256>>>(x);
    transpose_split_kernel<<<dim3(32, 32, 4), dim3(32, 8)>>>(wq, wk, wv, wo);

    qkv_mma_kernel<<<dim3(8, 32, 3), 256, GEMM_SMEM>>>(bq, bk, bv);

    split_v_kernel<<<dim3(TSEQ / 64, BSZ * NH), 256>>>();

    attn_mma_kernel<<<dim3(8, BSZ * NH), 256, ATTN_SMEM>>>();

    oproj_mma_kernel<<<dim3(8, 32), 256, GEMM_SMEM>>>(bo, out);
}